// round 15
// baseline (speedup 1.0000x reference)
#include <cuda_runtime.h>
#include <cuda_bf16.h>

#define CCH   256
#define HH    360
#define WW    360
#define NPTS  1024
#define CPB   8
#define NPAIR (CPB / 2)   // 4 center pairs per block

typedef unsigned long long ull;

// Scratch: a1[m][k] = f1 @ w3 ; a2p[n][k] = b3[k] - (f2 @ w3)[n][k]
__device__ float g_a1[NPTS * 32];
__device__ float g_a2p[NPTS * 32];

#define FFMA2(acc, x, w) \
    asm("fma.rn.f32x2 %0, %1, %2, %0;" : "+l"(acc) : "l"(x), "l"(w))
#define FADD2(d, a, b) \
    asm("add.rn.f32x2 %0, %1, %2;" : "=l"(d) : "l"(a), "l"(b))

__device__ __forceinline__ ull pack2(float a, float b) {
    ull r;
    asm("mov.b64 %0, {%1, %2};" : "=l"(r) : "f"(a), "f"(b));
    return r;
}
__device__ __forceinline__ float2 unpack2(ull v) {
    float2 f;
    asm("mov.b64 {%0, %1}, %2;" : "=f"(f.x), "=f"(f.y) : "l"(v));
    return f;
}

// ---------------------------------------------------------------------------
// Kernel 1: gather + 256->256->128 MLP (relu) + @w3 projection (b3 folded).
// CPB=8 centers per block (4 f32x2 center-pairs), 256 threads, 256 blocks
// (~2 CTAs/SM: cross-CTA latency hiding; grid was 128 < 148 SMs before).
// NO split-K: each thread reduces its full channel range -> only 3 barriers.
// smem (36KB, no overlays): xs2 8KB | h1p 8KB | h2p 4KB | w3s 16KB.
// ---------------------------------------------------------------------------
__global__ __launch_bounds__(256) void project_kernel(
    const float* __restrict__ feature,
    const int*   __restrict__ idx1,
    const int*   __restrict__ idx2,
    const float* __restrict__ w1, const float* __restrict__ b1,
    const float* __restrict__ w2, const float* __restrict__ b2,
    const float* __restrict__ w3, const float* __restrict__ b3)
{
    __shared__ float2 xs2[NPAIR][256];   // 8KB gathered features
    __shared__ float2 h1p[NPAIR][256];   // 8KB layer1 out
    __shared__ float2 h2p[NPAIR][128];   // 4KB layer2 out
    __shared__ float  w3s[128 * 32];     // 16KB

    const int tid = threadIdx.x;
    const int g0  = blockIdx.x * CPB;
    const bool frame2 = (g0 >= NPTS);
    const int* __restrict__ idx = frame2 ? idx2 : idx1;
    const int  i0 = frame2 ? (g0 - NPTS) : g0;

    // ---- stage w3 (16KB) — independent of gather, overlaps its latency
    {
        const float4* src = (const float4*)w3;
        float4* dst = (float4*)w3s;
        #pragma unroll
        for (int i = 0; i < 4; i++) dst[tid + i * 256] = src[tid + i * 256];
    }

    // ---- gather: 8 centers x 256 channels = 2048 loads over 256 threads
    #pragma unroll
    for (int i = 0; i < CPB; i++) {
        int e  = tid + i * 256;
        int t  = e >> 8;
        int ch = e & 255;
        int b  = __ldg(&idx[i0 + t]);
        int hh = __ldg(&idx[NPTS + i0 + t]);
        int ww = __ldg(&idx[2 * NPTS + i0 + t]);
        long off = (((long)b * CCH + ch) * HH + hh) * (long)WW + ww;
        ((float*)&xs2[t >> 1][ch])[t & 1] = __ldg(&feature[off]);
    }
    __syncthreads();

    // ---- layer 1: h1 = relu(x @ w1 + b1); thread tid owns output col tid,
    // full 256-channel reduction (no split-K).
    {
        const int j = tid;
        ull acc[NPAIR];
        {
            float bb = b1[j];
            ull init = pack2(bb, bb);
            #pragma unroll
            for (int p = 0; p < NPAIR; p++) acc[p] = init;
        }
        #pragma unroll 2
        for (int c = 0; c < 256; c += 4) {
            float v0 = w1[(c + 0) * 256 + j];
            float v1 = w1[(c + 1) * 256 + j];
            float v2 = w1[(c + 2) * 256 + j];
            float v3 = w1[(c + 3) * 256 + j];
            ull p0 = pack2(v0, v0), p1 = pack2(v1, v1);
            ull p2 = pack2(v2, v2), p3 = pack2(v3, v3);
            #pragma unroll
            for (int p = 0; p < NPAIR; p++) {
                ulonglong2 qa = *(const ulonglong2*)&xs2[p][c];
                ulonglong2 qb = *(const ulonglong2*)&xs2[p][c + 2];
                FFMA2(acc[p], qa.x, p0);
                FFMA2(acc[p], qa.y, p1);
                FFMA2(acc[p], qb.x, p2);
                FFMA2(acc[p], qb.y, p3);
            }
        }
        #pragma unroll
        for (int p = 0; p < NPAIR; p++) {
            float2 f = unpack2(acc[p]);
            h1p[p][j] = make_float2(fmaxf(f.x, 0.0f), fmaxf(f.y, 0.0f));
        }
    }
    __syncthreads();

    // ---- layer 2: h2 = relu(h1 @ w2 + b2)
    // thread (j2 = tid&127, ph = tid>>7): col j2, pairs ph*2 .. ph*2+1.
    {
        const int j2 = tid & 127;
        const int ph = tid >> 7;
        const int pb = ph * 2;
        ull acc[2];
        {
            float bb = b2[j2];
            ull init = pack2(bb, bb);
            acc[0] = init; acc[1] = init;
        }
        #pragma unroll 2
        for (int c = 0; c < 256; c += 4) {
            float v0 = w2[(c + 0) * 128 + j2];
            float v1 = w2[(c + 1) * 128 + j2];
            float v2 = w2[(c + 2) * 128 + j2];
            float v3 = w2[(c + 3) * 128 + j2];
            ull p0 = pack2(v0, v0), p1 = pack2(v1, v1);
            ull p2 = pack2(v2, v2), p3 = pack2(v3, v3);
            #pragma unroll
            for (int u = 0; u < 2; u++) {
                int p = pb + u;
                ulonglong2 qa = *(const ulonglong2*)&h1p[p][c];
                ulonglong2 qb = *(const ulonglong2*)&h1p[p][c + 2];
                FFMA2(acc[u], qa.x, p0);
                FFMA2(acc[u], qa.y, p1);
                FFMA2(acc[u], qb.x, p2);
                FFMA2(acc[u], qb.y, p3);
            }
        }
        #pragma unroll
        for (int u = 0; u < 2; u++) {
            float2 f = unpack2(acc[u]);
            h2p[pb + u][j2] = make_float2(fmaxf(f.x, 0.0f), fmaxf(f.y, 0.0f));
        }
    }
    __syncthreads();

    // ---- layer 3 (projection): a = h2 @ w3, b3 folded for frame 2.
    // 8 warps, warp w -> center w; lane k -> output dim k.
    {
        const int w = tid >> 5;       // 0..7 = center
        const int k = tid & 31;
        const int p = w >> 1;
        const int hl = w & 1;
        float acc0 = 0.0f, acc1 = 0.0f, acc2 = 0.0f, acc3 = 0.0f;
        #pragma unroll 8
        for (int d = 0; d < 128; d += 4) {
            float hv0 = ((const float*)&h2p[p][d + 0])[hl];
            float hv1 = ((const float*)&h2p[p][d + 1])[hl];
            float hv2 = ((const float*)&h2p[p][d + 2])[hl];
            float hv3 = ((const float*)&h2p[p][d + 3])[hl];
            acc0 = fmaf(hv0, w3s[(d + 0) * 32 + k], acc0);
            acc1 = fmaf(hv1, w3s[(d + 1) * 32 + k], acc1);
            acc2 = fmaf(hv2, w3s[(d + 2) * 32 + k], acc2);
            acc3 = fmaf(hv3, w3s[(d + 3) * 32 + k], acc3);
        }
        float r = (acc0 + acc1) + (acc2 + acc3);
        int gg = g0 + w;
        if (!frame2) {
            g_a1[gg * 32 + k] = r;
        } else {
            g_a2p[(gg - NPTS) * 32 + k] = b3[k] - r;
        }
    }
}

// ---------------------------------------------------------------------------
// Kernel 2: out[m,n] = b4 + sum_k relu(a1[m,k] + a2p[n,k]) * w4[k]
// 256 threads (each owns one n), m-tile 8, grid (4, 128) = 512 CTAs
// (~3.5 CTAs/SM). Loop interchange keeps regs low (acc[8] = 16 regs);
// prologue is tiny so the r5-style m-tile-8 regression doesn't apply.
// ---------------------------------------------------------------------------
__global__ __launch_bounds__(256) void pair_kernel(
    const float* __restrict__ w4,
    const float* __restrict__ b4,
    float*       __restrict__ out)
{
    __shared__ float a1s[8 * 32];    // 1KB
    __shared__ float2 w4s[16];       // 128B packed (w4[2i], w4[2i+1]) pairs

    const int tid = threadIdx.x;
    const int n   = blockIdx.x * 256 + tid;
    const int m0  = blockIdx.y * 8;

    // stage a1 tile (8 x 32 = 256 floats) via float4
    if (tid < 64)
        ((float4*)a1s)[tid] = ((const float4*)(g_a1 + m0 * 32))[tid];
    if (tid < 16)
        w4s[tid] = ((const float2*)w4)[tid];

    const float bias = b4[0];
    const float4* a2row = (const float4*)(g_a2p + (long)n * 32);
    __syncthreads();

    ull acc[8];
    {
        ull init = pack2(bias, 0.0f);
        #pragma unroll
        for (int m = 0; m < 8; m++) acc[m] = init;
    }

    #pragma unroll 1
    for (int v = 0; v < 8; v++) {          // 8 chunks of 4 dims
        float4 av = a2row[v];              // this thread's a2p chunk
        ull a2p0 = pack2(av.x, av.y);
        ull a2p1 = pack2(av.z, av.w);
        ulonglong2 wv = ((const ulonglong2*)w4s)[v];   // broadcast
        #pragma unroll
        for (int m = 0; m < 8; m++) {
            ulonglong2 qa = *(const ulonglong2*)&a1s[m * 32 + 4 * v];
            ull s0, s1;
            FADD2(s0, qa.x, a2p0);
            FADD2(s1, qa.y, a2p1);
            float2 f0 = unpack2(s0), f1 = unpack2(s1);
            s0 = pack2(fmaxf(f0.x, 0.0f), fmaxf(f0.y, 0.0f));
            s1 = pack2(fmaxf(f1.x, 0.0f), fmaxf(f1.y, 0.0f));
            FFMA2(acc[m], s0, wv.x);
            FFMA2(acc[m], s1, wv.y);
        }
    }

    #pragma unroll
    for (int m = 0; m < 8; m++) {
        float2 r = unpack2(acc[m]);
        out[(long)(m0 + m) * 1024 + n] = r.x + r.y;
    }
}

// ---------------------------------------------------------------------------
extern "C" void kernel_launch(void* const* d_in, const int* in_sizes, int n_in,
                              void* d_out, int out_size)
{
    const float* feature = (const float*)d_in[0];
    const int*   idx1    = (const int*)  d_in[1];
    const int*   idx2    = (const int*)  d_in[2];
    const float* w1      = (const float*)d_in[3];
    const float* b1      = (const float*)d_in[4];
    const float* w2      = (const float*)d_in[5];
    const float* b2      = (const float*)d_in[6];
    const float* w3      = (const float*)d_in[7];
    const float* b3      = (const float*)d_in[8];
    const float* w4      = (const float*)d_in[9];
    const float* b4      = (const float*)d_in[10];
    float* out = (float*)d_out;

    project_kernel<<<(2 * NPTS) / CPB, 256>>>(feature, idx1, idx2,
                                              w1, b1, w2, b2, w3, b3);
    dim3 grid2(NPTS / 256, NPTS / 8);
    pair_kernel<<<grid2, 256>>>(w4, b4, out);
}

// round 16
// speedup vs baseline: 1.2529x; 1.2529x over previous
#include <cuda_runtime.h>
#include <cuda_bf16.h>

#define CCH   256
#define HH    360
#define WW    360
#define NPTS  1024
#define CPB   16
#define NPAIR (CPB / 2)   // 8 center pairs per block

typedef unsigned long long ull;

// Scratch: a1[m][k] = f1 @ w3 ; a2p[n][k] = b3[k] - (f2 @ w3)[n][k]
__device__ float g_a1[NPTS * 32];
__device__ float g_a2p[NPTS * 32];

#define FFMA2(acc, x, w) \
    asm("fma.rn.f32x2 %0, %1, %2, %0;" : "+l"(acc) : "l"(x), "l"(w))
#define FADD2(d, a, b) \
    asm("add.rn.f32x2 %0, %1, %2;" : "=l"(d) : "l"(a), "l"(b))

__device__ __forceinline__ ull pack2(float a, float b) {
    ull r;
    asm("mov.b64 %0, {%1, %2};" : "=l"(r) : "f"(a), "f"(b));
    return r;
}
__device__ __forceinline__ float2 unpack2(ull v) {
    float2 f;
    asm("mov.b64 {%0, %1}, %2;" : "=f"(f.x), "=f"(f.y) : "l"(v));
    return f;
}

// ---------------------------------------------------------------------------
// Kernel 1: gather + 256->256->128 MLP (relu) + @w3 projection (b3 folded).
// 16 centers per block (8 f32x2 center-pairs), 512 threads, 128 blocks.
// r8/r14 structure (best measured). ONLY change: MLP c-loop unroll 2 -> 4
// (16 weight LDGs in flight instead of 8; longer FFMA2 runs between loads).
// Shared memory (48KB, overlaid):
//   smemA: xs2[8][256]  -> w3s[128*32] after layer1
//   smemB: part1[8][256] -> part2[8][128] | h2p[8][128]
//   smemC: h1p[8][256]
// ---------------------------------------------------------------------------
__global__ __launch_bounds__(512) void project_kernel(
    const float* __restrict__ feature,
    const int*   __restrict__ idx1,
    const int*   __restrict__ idx2,
    const float* __restrict__ w1, const float* __restrict__ b1,
    const float* __restrict__ w2, const float* __restrict__ b2,
    const float* __restrict__ w3, const float* __restrict__ b3)
{
    __shared__ float2 smemA[NPAIR * 256];   // 16KB
    __shared__ float2 smemB[NPAIR * 256];   // 16KB
    __shared__ float2 smemC[NPAIR * 256];   // 16KB

    float2 (*xs2)[256] = (float2 (*)[256])smemA;
    float*  w3s        = (float*)smemA;
    float2 (*part1)[256] = (float2 (*)[256])smemB;
    float2* part2      = smemB;              // [8][128] float2 = 8KB
    float2 (*h2p)[128] = (float2 (*)[128])(smemB + 1024); // 8KB
    float2 (*h1p)[256] = (float2 (*)[256])smemC;

    const int tid = threadIdx.x;
    const int g0  = blockIdx.x * CPB;
    const bool frame2 = (g0 >= NPTS);
    const int* __restrict__ idx = frame2 ? idx2 : idx1;
    const int  i0 = frame2 ? (g0 - NPTS) : g0;

    // ---- gather: 16 centers x 256 channels = 4096 loads over 512 threads
    #pragma unroll
    for (int i = 0; i < 8; i++) {
        int e  = tid + i * 512;
        int t  = e >> 8;
        int ch = e & 255;
        int b  = __ldg(&idx[i0 + t]);
        int hh = __ldg(&idx[NPTS + i0 + t]);
        int ww = __ldg(&idx[2 * NPTS + i0 + t]);
        long off = (((long)b * CCH + ch) * HH + hh) * (long)WW + ww;
        ((float*)&xs2[t >> 1][ch])[t & 1] = __ldg(&feature[off]);
    }
    __syncthreads();

    // ---- layer 1: h1 = relu(x @ w1 + b1)
    // thread (j = tid&255, h = tid>>8): output col j, channel half h.
    {
        const int j = tid & 255;
        const int h = tid >> 8;
        const int cbase = h * 128;
        ull acc[NPAIR];
        {
            ull init;
            if (h) init = 0ULL;
            else { float bb = b1[j]; init = pack2(bb, bb); }
            #pragma unroll
            for (int p = 0; p < NPAIR; p++) acc[p] = init;
        }
        #pragma unroll 4
        for (int c0 = 0; c0 < 128; c0 += 4) {
            int c = cbase + c0;
            float v0 = w1[(c + 0) * 256 + j];
            float v1 = w1[(c + 1) * 256 + j];
            float v2 = w1[(c + 2) * 256 + j];
            float v3 = w1[(c + 3) * 256 + j];
            ull p0 = pack2(v0, v0), p1 = pack2(v1, v1);
            ull p2 = pack2(v2, v2), p3 = pack2(v3, v3);
            #pragma unroll
            for (int p = 0; p < NPAIR; p++) {
                ulonglong2 qa = *(const ulonglong2*)&xs2[p][c];
                ulonglong2 qb = *(const ulonglong2*)&xs2[p][c + 2];
                FFMA2(acc[p], qa.x, p0);
                FFMA2(acc[p], qa.y, p1);
                FFMA2(acc[p], qb.x, p2);
                FFMA2(acc[p], qb.y, p3);
            }
        }
        if (h) {
            #pragma unroll
            for (int p = 0; p < NPAIR; p++)
                part1[p][j] = unpack2(acc[p]);
        }
        __syncthreads();   // xs2 dead; part1 ready
        if (!h) {
            #pragma unroll
            for (int p = 0; p < NPAIR; p++) {
                float2 f = unpack2(acc[p]);
                float2 g = part1[p][j];
                h1p[p][j] = make_float2(fmaxf(f.x + g.x, 0.0f),
                                        fmaxf(f.y + g.y, 0.0f));
            }
        } else {
            // h==1 threads stage w3 into the freed xs2 region
            const float4* src = (const float4*)w3;
            float4* dst = (float4*)w3s;
            int l = tid - 256;
            #pragma unroll
            for (int i = 0; i < 4; i++) dst[l + i * 256] = src[l + i * 256];
        }
    }
    __syncthreads();

    // ---- layer 2: h2 = relu(h1 @ w2 + b2)
    // thread (j2 = tid&127, q = tid>>7): qc = channel half, qp = pair half.
    {
        const int j2 = tid & 127;
        const int q  = tid >> 7;
        const int qc = q & 1;
        const int qp = q >> 1;
        const int cbase = qc * 128;
        const int pb = qp * 4;
        ull acc[4];
        {
            ull init;
            if (qc) init = 0ULL;
            else { float bb = b2[j2]; init = pack2(bb, bb); }
            #pragma unroll
            for (int u = 0; u < 4; u++) acc[u] = init;
        }
        #pragma unroll 4
        for (int c0 = 0; c0 < 128; c0 += 4) {
            int c = cbase + c0;
            float v0 = w2[(c + 0) * 128 + j2];
            float v1 = w2[(c + 1) * 128 + j2];
            float v2 = w2[(c + 2) * 128 + j2];
            float v3 = w2[(c + 3) * 128 + j2];
            ull p0 = pack2(v0, v0), p1 = pack2(v1, v1);
            ull p2 = pack2(v2, v2), p3 = pack2(v3, v3);
            #pragma unroll
            for (int u = 0; u < 4; u++) {
                int p = pb + u;
                ulonglong2 qa = *(const ulonglong2*)&h1p[p][c];
                ulonglong2 qb = *(const ulonglong2*)&h1p[p][c + 2];
                FFMA2(acc[u], qa.x, p0);
                FFMA2(acc[u], qa.y, p1);
                FFMA2(acc[u], qb.x, p2);
                FFMA2(acc[u], qb.y, p3);
            }
        }
        if (qc) {
            #pragma unroll
            for (int u = 0; u < 4; u++)
                part2[(qp * 4 + u) * 128 + j2] = unpack2(acc[u]);
        }
        __syncthreads();   // part1 dead; part2 ready
        if (!qc) {
            #pragma unroll
            for (int u = 0; u < 4; u++) {
                float2 f = unpack2(acc[u]);
                float2 g = part2[(qp * 4 + u) * 128 + j2];
                h2p[pb + u][j2] = make_float2(fmaxf(f.x + g.x, 0.0f),
                                              fmaxf(f.y + g.y, 0.0f));
            }
        }
    }
    __syncthreads();

    // ---- layer 3 (projection): a = h2 @ w3, b3 folded for frame 2.
    // 16 warps, warp w -> center w; lane k -> output dim k.
    {
        const int w = tid >> 5;       // 0..15 = center
        const int k = tid & 31;
        const int p = w >> 1;
        const int hl = w & 1;
        float acc0 = 0.0f, acc1 = 0.0f, acc2 = 0.0f, acc3 = 0.0f;
        #pragma unroll 8
        for (int d = 0; d < 128; d += 4) {
            float hv0 = ((const float*)&h2p[p][d + 0])[hl];
            float hv1 = ((const float*)&h2p[p][d + 1])[hl];
            float hv2 = ((const float*)&h2p[p][d + 2])[hl];
            float hv3 = ((const float*)&h2p[p][d + 3])[hl];
            acc0 = fmaf(hv0, w3s[(d + 0) * 32 + k], acc0);
            acc1 = fmaf(hv1, w3s[(d + 1) * 32 + k], acc1);
            acc2 = fmaf(hv2, w3s[(d + 2) * 32 + k], acc2);
            acc3 = fmaf(hv3, w3s[(d + 3) * 32 + k], acc3);
        }
        float r = (acc0 + acc1) + (acc2 + acc3);
        int gg = g0 + w;
        if (!frame2) {
            g_a1[gg * 32 + k] = r;
        } else {
            g_a2p[(gg - NPTS) * 32 + k] = b3[k] - r;
        }
    }
}

// ---------------------------------------------------------------------------
// Kernel 2: out[m,n] = b4 + sum_k relu(a1[m,k] + a2p[n,k]) * w4[k]
// 256 threads (each owns one n), m-tile 16, grid (4, 64) = 256 CTAs.
// Byte-identical to round-14 (best measured pair: 9.86us, regs=64).
// ---------------------------------------------------------------------------
__global__ __launch_bounds__(256) void pair_kernel(
    const float* __restrict__ w4,
    const float* __restrict__ b4,
    float*       __restrict__ out)
{
    __shared__ float a1s[16 * 32];   // 2KB
    __shared__ float2 w4s[16];       // 128B: packed (w4[2i], w4[2i+1]) pairs

    const int tid = threadIdx.x;
    const int n   = blockIdx.x * 256 + tid;
    const int m0  = blockIdx.y * 16;

    // stage a1 tile (16 x 32 = 512 floats) via float4
    if (tid < 128)
        ((float4*)a1s)[tid] = ((const float4*)(g_a1 + m0 * 32))[tid];
    // stage w4 pairs
    if (tid < 16)
        w4s[tid] = ((const float2*)w4)[tid];

    const float bias = b4[0];
    const float4* a2row = (const float4*)(g_a2p + (long)n * 32);
    __syncthreads();

    // accumulators: one packed f32x2 per m-row
    ull acc[16];
    {
        ull init = pack2(bias, 0.0f);
        #pragma unroll
        for (int m = 0; m < 16; m++) acc[m] = init;
    }

    #pragma unroll 1
    for (int v = 0; v < 8; v++) {          // 8 chunks of 4 dims
        float4 av = a2row[v];              // this thread's a2p chunk (L1 hot)
        ull a2p0 = pack2(av.x, av.y);
        ull a2p1 = pack2(av.z, av.w);
        ulonglong2 wv = ((const ulonglong2*)w4s)[v];   // broadcast
        #pragma unroll
        for (int m = 0; m < 16; m++) {
            ulonglong2 qa = *(const ulonglong2*)&a1s[m * 32 + 4 * v];
            ull s0, s1;
            FADD2(s0, qa.x, a2p0);
            FADD2(s1, qa.y, a2p1);
            float2 f0 = unpack2(s0), f1 = unpack2(s1);
            s0 = pack2(fmaxf(f0.x, 0.0f), fmaxf(f0.y, 0.0f));
            s1 = pack2(fmaxf(f1.x, 0.0f), fmaxf(f1.y, 0.0f));
            FFMA2(acc[m], s0, wv.x);
            FFMA2(acc[m], s1, wv.y);
        }
    }

    #pragma unroll
    for (int m = 0; m < 16; m++) {
        float2 r = unpack2(acc[m]);
        out[(long)(m0 + m) * 1024 + n] = r.x + r.y;
    }
}

// ---------------------------------------------------------------------------
extern "C" void kernel_launch(void* const* d_in, const int* in_sizes, int n_in,
                              void* d_out, int out_size)
{
    const float* feature = (const float*)d_in[0];
    const int*   idx1    = (const int*)  d_in[1];
    const int*   idx2    = (const int*)  d_in[2];
    const float* w1      = (const float*)d_in[3];
    const float* b1      = (const float*)d_in[4];
    const float* w2      = (const float*)d_in[5];
    const float* b2      = (const float*)d_in[6];
    const float* w3      = (const float*)d_in[7];
    const float* b3      = (const float*)d_in[8];
    const float* w4      = (const float*)d_in[9];
    const float* b4      = (const float*)d_in[10];
    float* out = (float*)d_out;

    project_kernel<<<(2 * NPTS) / CPB, 512>>>(feature, idx1, idx2,
                                              w1, b1, w2, b2, w3, b3);
    dim3 grid2(NPTS / 256, NPTS / 16);
    pair_kernel<<<grid2, 256>>>(w4, b4, out);
}